// round 8
// baseline (speedup 1.0000x reference)
#include <cuda_runtime.h>
#include <math.h>

#define N_AG 262144
#define GRID_SZ 1024
#define NCELL (GRID_SZ*GRID_SZ)
#define NCH 8
#define HID 64
#define DT 0.1f
#define DECAY 0.99f
#define SENSOR_LEN 3.0f
// cos(0.6), sin(0.6)
#define COS_A 0.825335614909678f
#define SIN_A 0.564642473395035f

typedef unsigned long long ull;

// Scratch (__device__ globals; no allocation allowed)
__device__ int    g_claim[NCELL];        // 4 MB : winning agent id per cell (reset by winners)
__device__ float4 g_boxA[NCELL];         // 16 MB: 3x3 box sums, channels 0-3
__device__ float4 g_boxB[NCELL];         // 16 MB: 3x3 box sums, channels 4-7

__device__ __forceinline__ ull pk2(float lo, float hi) {
    ull r; asm("mov.b64 %0, {%1, %2};" : "=l"(r) : "f"(lo), "f"(hi)); return r;
}
__device__ __forceinline__ void upk2(ull v, float& lo, float& hi) {
    asm("mov.b64 {%0, %1}, %2;" : "=f"(lo), "=f"(hi) : "l"(v));
}
__device__ __forceinline__ ull fma2(ull a, ull b, ull c) {
    ull d; asm("fma.rn.f32x2 %0, %1, %2, %3;" : "=l"(d) : "l"(a), "l"(b), "l"(c)); return d;
}

// Pass 0: block = one lattice row. Coalesced float4 loads -> column sums in smem,
// decayed output, coalesced box-sum stores (stride-256 cell remap).
// Also: this thread claims agent tid's deposit cell (atomicMax, last-id-wins).
__global__ __launch_bounds__(256) void prep_kernel(const float* __restrict__ lat,
                                                   const float* __restrict__ pos,
                                                   float* __restrict__ out_lat) {
    __shared__ float cs_s[NCH][GRID_SZ];
    int x = blockIdx.x;
    int t = threadIdx.x;
    int y0 = t << 2;
    int r0 = ((x + 1023) & 1023) << 10;
    int r1 = x << 10;
    int r2 = ((x + 1) & 1023) << 10;

    // agent claim (one agent per prep thread; coalesced pos read)
    int a = blockIdx.x * 256 + t;
    float pax = pos[a], pay = pos[N_AG + a];
    int ca = ((((int)rintf(pax)) & 1023) << 10) | (((int)rintf(pay)) & 1023);
    atomicMax(&g_claim[ca], a);

#pragma unroll
    for (int c = 0; c < NCH; c++) {
        const float* L = lat + ((size_t)c << 20);
        float4 va = __ldg((const float4*)&L[r0 | y0]);
        float4 vb = __ldg((const float4*)&L[r1 | y0]);
        float4 vd = __ldg((const float4*)&L[r2 | y0]);
        *reinterpret_cast<float4*>(&cs_s[c][y0]) =
            make_float4(va.x + vb.x + vd.x, va.y + vb.y + vd.y,
                        va.z + vb.z + vd.z, va.w + vb.w + vd.w);
        *reinterpret_cast<float4*>(&out_lat[((size_t)c << 20) | (r1 | y0)]) =
            make_float4(vb.x * DECAY, vb.y * DECAY, vb.z * DECAY, vb.w * DECAY);
    }
    __syncthreads();

#pragma unroll
    for (int i = 0; i < 4; i++) {
        int y  = t + (i << 8);               // stride-256 cell ownership
        int ym = (y + 1023) & 1023;
        int yp = (y + 1) & 1023;
        float v[NCH];
#pragma unroll
        for (int c = 0; c < NCH; c++)
            v[c] = cs_s[c][ym] + cs_s[c][y] + cs_s[c][yp];
        int cell = r1 | y;
        g_boxA[cell] = make_float4(v[0], v[1], v[2], v[3]);   // 16B lane stride
        g_boxB[cell] = make_float4(v[4], v[5], v[6], v[7]);
    }
}

// sense one agent -> 24 plain floats
__device__ __forceinline__ void sense_agent(float px, float py, float vx, float vy,
                                            float* xa) {
    float invn = rsqrtf(fmaf(vx, vx, vy * vy));
    float c0 = vx * invn, s0 = vy * invn;
    float cs[3], sn[3];
    cs[0] = c0;                        sn[0] = s0;
    cs[1] = c0 * COS_A - s0 * SIN_A;   sn[1] = s0 * COS_A + c0 * SIN_A;
    cs[2] = c0 * COS_A + s0 * SIN_A;   sn[2] = s0 * COS_A - c0 * SIN_A;
#pragma unroll
    for (int s = 0; s < 3; s++) {
        int cx = (int)rintf(fmaf(SENSOR_LEN, cs[s], px));
        int cy = (int)rintf(fmaf(SENSOR_LEN, sn[s], py));
        int cell = ((cx & (GRID_SZ - 1)) << 10) | (cy & (GRID_SZ - 1));
        float4 a0 = __ldg(&g_boxA[cell]);
        float4 a1 = __ldg(&g_boxB[cell]);
        xa[s * 8 + 0] = a0.x; xa[s * 8 + 1] = a0.y; xa[s * 8 + 2] = a0.z; xa[s * 8 + 3] = a0.w;
        xa[s * 8 + 4] = a1.x; xa[s * 8 + 5] = a1.y; xa[s * 8 + 6] = a1.z; xa[s * 8 + 7] = a1.w;
    }
}

// Pass 1: two agents per thread, (A,B)-packed f32x2 MLP with duplicated weights,
// fused winner-deposit + claim reset.
__global__ __launch_bounds__(128, 4) void agent_kernel(
    const float* __restrict__ pos, const float* __restrict__ vel,
    const float* __restrict__ W1, const float* __restrict__ b1,
    const float* __restrict__ W2, const float* __restrict__ b2,
    const float* __restrict__ lat, float* __restrict__ out) {
    __shared__ ull   sW1d[24 * HID];   // (w,w) duplicated pairs, [k][j], 12 KB
    __shared__ ull   sb1d[HID];        // (b,b)
    __shared__ float sW2p[HID * 12];   // padded [j][12]
    __shared__ float sO0[12];
    int t = threadIdx.x;
    for (int i = t; i < 24 * HID; i += 128) { float w = W1[i]; sW1d[i] = pk2(w, w); }
    for (int i = t; i < HID * 12; i += 128) { int j = i / 12, k = i - j * 12; sW2p[i] = (k < 10) ? W2[j * 10 + k] : 0.f; }
    if (t < HID) { float b = b1[t]; sb1d[t] = pk2(b, b); }
    if (t < 12)  sO0[t] = (t < 10) ? b2[t] : 0.f;
    __syncthreads();

    int g = blockIdx.x * 128 + t;           // handles agents 2g, 2g+1
    float2 pxv = ((const float2*)pos)[g];
    float2 pyv = ((const float2*)(pos + N_AG))[g];
    float2 vxv = ((const float2*)vel)[g];
    float2 vyv = ((const float2*)(vel + N_AG))[g];

    float xaA[24], xaB[24];
    sense_agent(pxv.x, pyv.x, vxv.x, vyv.x, xaA);
    sense_agent(pxv.y, pyv.y, vxv.y, vyv.y, xaB);
    ull xAB[24];
#pragma unroll
    for (int k = 0; k < 24; k++) xAB[k] = pk2(xaA[k], xaB[k]);

    ull oA[6], oB[6];
#pragma unroll
    for (int k = 0; k < 6; k++) { ull z = pk2(sO0[2 * k], sO0[2 * k + 1]); oA[k] = z; oB[k] = z; }

#pragma unroll 1
    for (int j = 0; j < HID; j += 4) {
        ull acc0 = sb1d[j], acc1 = sb1d[j + 1], acc2 = sb1d[j + 2], acc3 = sb1d[j + 3];
#pragma unroll
        for (int k = 0; k < 24; k++) {
            ulonglong2 w01 = *reinterpret_cast<const ulonglong2*>(&sW1d[k * HID + j]);
            ulonglong2 w23 = *reinterpret_cast<const ulonglong2*>(&sW1d[k * HID + j + 2]);
            acc0 = fma2(xAB[k], w01.x, acc0);
            acc1 = fma2(xAB[k], w01.y, acc1);
            acc2 = fma2(xAB[k], w23.x, acc2);
            acc3 = fma2(xAB[k], w23.y, acc3);
        }
        ull accs[4] = {acc0, acc1, acc2, acc3};
#pragma unroll
        for (int jj = 0; jj < 4; jj++) {
            float aA, aB, ha, hb;
            upk2(accs[jj], aA, aB);
            asm("tanh.approx.f32 %0, %1;" : "=f"(ha) : "f"(aA));
            asm("tanh.approx.f32 %0, %1;" : "=f"(hb) : "f"(aB));
            ull h2a = pk2(ha, ha), h2b = pk2(hb, hb);
            const ulonglong2* wp = reinterpret_cast<const ulonglong2*>(&sW2p[(j + jj) * 12]);
            ulonglong2 u0 = wp[0], u1 = wp[1], u2 = wp[2];
            oA[0] = fma2(h2a, u0.x, oA[0]); oA[1] = fma2(h2a, u0.y, oA[1]);
            oA[2] = fma2(h2a, u1.x, oA[2]); oA[3] = fma2(h2a, u1.y, oA[3]);
            oA[4] = fma2(h2a, u2.x, oA[4]); oA[5] = fma2(h2a, u2.y, oA[5]);
            oB[0] = fma2(h2b, u0.x, oB[0]); oB[1] = fma2(h2b, u0.y, oB[1]);
            oB[2] = fma2(h2b, u1.x, oB[2]); oB[3] = fma2(h2b, u1.y, oB[3]);
            oB[4] = fma2(h2b, u2.x, oB[4]); oB[5] = fma2(h2b, u2.y, oB[5]);
        }
    }
    float fA[12], fB[12];
#pragma unroll
    for (int k = 0; k < 6; k++) { upk2(oA[k], fA[2 * k], fA[2 * k + 1]); upk2(oB[k], fB[2 * k], fB[2 * k + 1]); }

    // ---- pos/vel outputs ----
    float npxA = fmaf(fA[0], DT, pxv.x), npyA = fmaf(fA[1], DT, pyv.x);
    float npxB = fmaf(fB[0], DT, pxv.y), npyB = fmaf(fB[1], DT, pyv.y);
    if (npxA >= (float)GRID_SZ) npxA -= (float)GRID_SZ; else if (npxA < 0.f) npxA += (float)GRID_SZ;
    if (npyA >= (float)GRID_SZ) npyA -= (float)GRID_SZ; else if (npyA < 0.f) npyA += (float)GRID_SZ;
    if (npxB >= (float)GRID_SZ) npxB -= (float)GRID_SZ; else if (npxB < 0.f) npxB += (float)GRID_SZ;
    if (npyB >= (float)GRID_SZ) npyB -= (float)GRID_SZ; else if (npyB < 0.f) npyB += (float)GRID_SZ;

    ((float2*)out)[g]              = make_float2(npxA, npxB);
    ((float2*)(out + N_AG))[g]     = make_float2(npyA, npyB);
    ((float2*)(out + 2 * N_AG))[g] = make_float2(fA[0], fB[0]);
    ((float2*)(out + 3 * N_AG))[g] = make_float2(fA[1], fB[1]);

    // ---- fused deposit: winner writes relu(cur + DT*dp)*DECAY, resets claim ----
    float* out_lat = out + 4 * N_AG;
    int a0 = 2 * g, a1 = 2 * g + 1;
    int cellA = ((((int)rintf(pxv.x)) & 1023) << 10) | (((int)rintf(pyv.x)) & 1023);
    int cellB = ((((int)rintf(pxv.y)) & 1023) << 10) | (((int)rintf(pyv.y)) & 1023);
    if (g_claim[cellA] == a0) {
#pragma unroll
        for (int c = 0; c < NCH; c++) {
            float cur = __ldg(&lat[(c << 20) | cellA]);
            out_lat[(c << 20) | cellA] = fmaxf(fmaf(DT, fA[2 + c], cur), 0.f) * DECAY;
        }
        g_claim[cellA] = -1;   // restore state for next graph replay
    }
    if (g_claim[cellB] == a1) {
#pragma unroll
        for (int c = 0; c < NCH; c++) {
            float cur = __ldg(&lat[(c << 20) | cellB]);
            out_lat[(c << 20) | cellB] = fmaxf(fmaf(DT, fB[2 + c], cur), 0.f) * DECAY;
        }
        g_claim[cellB] = -1;
    }
}

extern "C" void kernel_launch(void* const* d_in, const int* in_sizes, int n_in,
                              void* d_out, int out_size) {
    const float* pos = (const float*)d_in[0];   // (2, N)
    const float* vel = (const float*)d_in[1];   // (2, N)
    const float* lat = (const float*)d_in[2];   // (8, 1024, 1024)
    const float* W1  = (const float*)d_in[3];   // (24, 64)
    const float* b1  = (const float*)d_in[4];   // (64,)
    const float* W2  = (const float*)d_in[5];   // (64, 10)
    const float* b2  = (const float*)d_in[6];   // (10,)
    float* out = (float*)d_out;
    float* out_lat = out + 4 * N_AG;

    prep_kernel<<<GRID_SZ, 256>>>(lat, pos, out_lat);
    agent_kernel<<<N_AG / 2 / 128, 128>>>(pos, vel, W1, b1, W2, b2, lat, out);
}

// round 9
// speedup vs baseline: 1.0592x; 1.0592x over previous
#include <cuda_runtime.h>
#include <math.h>

#define N_AG 262144
#define GRID_SZ 1024
#define NCELL (GRID_SZ*GRID_SZ)
#define NCH 8
#define HID 64
#define DT 0.1f
#define DECAY 0.99f
#define SENSOR_LEN 3.0f
// cos(0.6), sin(0.6)
#define COS_A 0.825335614909678f
#define SIN_A 0.564642473395035f

typedef unsigned long long ull;

// Scratch (__device__ globals; no allocation allowed)
__device__ int    g_claim[NCELL];        // 4 MB : winning agent id per cell (reset by winners)
__device__ float4 g_boxA[NCELL];         // 16 MB: 3x3 box sums, channels 0-3
__device__ float4 g_boxB[NCELL];         // 16 MB: 3x3 box sums, channels 4-7

__device__ __forceinline__ ull pk2(float lo, float hi) {
    ull r; asm("mov.b64 %0, {%1, %2};" : "=l"(r) : "f"(lo), "f"(hi)); return r;
}
__device__ __forceinline__ void upk2(ull v, float& lo, float& hi) {
    asm("mov.b64 {%0, %1}, %2;" : "=f"(lo), "=f"(hi) : "l"(v));
}
__device__ __forceinline__ ull fma2(ull a, ull b, ull c) {
    ull d; asm("fma.rn.f32x2 %0, %1, %2, %3;" : "=l"(d) : "l"(a), "l"(b), "l"(c)); return d;
}

// Pass 0: block = one lattice row. Coalesced float4 loads -> column sums in smem,
// decayed output, coalesced box-sum stores (stride-256 cell remap).
// Also: this thread claims agent tid's deposit cell (atomicMax, last-id-wins).
__global__ __launch_bounds__(256) void prep_kernel(const float* __restrict__ lat,
                                                   const float* __restrict__ pos,
                                                   float* __restrict__ out_lat) {
    __shared__ float cs_s[NCH][GRID_SZ];
    int x = blockIdx.x;
    int t = threadIdx.x;
    int y0 = t << 2;
    int r0 = ((x + 1023) & 1023) << 10;
    int r1 = x << 10;
    int r2 = ((x + 1) & 1023) << 10;

    // agent claim (one agent per prep thread; coalesced pos read)
    int a = blockIdx.x * 256 + t;
    float pax = pos[a], pay = pos[N_AG + a];
    int ca = ((((int)rintf(pax)) & 1023) << 10) | (((int)rintf(pay)) & 1023);
    atomicMax(&g_claim[ca], a);

#pragma unroll
    for (int c = 0; c < NCH; c++) {
        const float* L = lat + ((size_t)c << 20);
        float4 va = __ldg((const float4*)&L[r0 | y0]);
        float4 vb = __ldg((const float4*)&L[r1 | y0]);
        float4 vd = __ldg((const float4*)&L[r2 | y0]);
        *reinterpret_cast<float4*>(&cs_s[c][y0]) =
            make_float4(va.x + vb.x + vd.x, va.y + vb.y + vd.y,
                        va.z + vb.z + vd.z, va.w + vb.w + vd.w);
        *reinterpret_cast<float4*>(&out_lat[((size_t)c << 20) | (r1 | y0)]) =
            make_float4(vb.x * DECAY, vb.y * DECAY, vb.z * DECAY, vb.w * DECAY);
    }
    __syncthreads();

#pragma unroll
    for (int i = 0; i < 4; i++) {
        int y  = t + (i << 8);               // stride-256 cell ownership
        int ym = (y + 1023) & 1023;
        int yp = (y + 1) & 1023;
        float v[NCH];
#pragma unroll
        for (int c = 0; c < NCH; c++)
            v[c] = cs_s[c][ym] + cs_s[c][y] + cs_s[c][yp];
        int cell = r1 | y;
        g_boxA[cell] = make_float4(v[0], v[1], v[2], v[3]);   // 16B lane stride
        g_boxB[cell] = make_float4(v[4], v[5], v[6], v[7]);
    }
}

// Pass 1: ONE agent per thread (low regs -> high occupancy), f32x2 MLP with
// on-the-fly input packing, fused winner-deposit + claim reset.
__global__ __launch_bounds__(256, 4) void agent_kernel(
    const float* __restrict__ pos, const float* __restrict__ vel,
    const float* __restrict__ W1, const float* __restrict__ b1,
    const float* __restrict__ W2, const float* __restrict__ b2,
    const float* __restrict__ lat, float* __restrict__ out) {
    __shared__ float sW1[24 * HID];    // row-major [k][j]: natural (w_j,w_j+1) pairs
    __shared__ float sW2p[HID * 12];   // padded [j][12]
    __shared__ float sb1[HID];
    __shared__ float sO0[12];
    int t = threadIdx.x;
    for (int i = t; i < 24 * HID; i += 256) sW1[i] = W1[i];
    for (int i = t; i < HID * 12; i += 256) { int j = i / 12, k = i - j * 12; sW2p[i] = (k < 10) ? W2[j * 10 + k] : 0.f; }
    if (t < HID) sb1[t] = b1[t];
    if (t < 12)  sO0[t] = (t < 10) ? b2[t] : 0.f;
    __syncthreads();

    int i = blockIdx.x * 256 + t;
    float px = pos[i], py = pos[N_AG + i];
    float vx = vel[i], vy = vel[N_AG + i];

    // direction via normalization + angle-addition
    float invn = rsqrtf(fmaf(vx, vx, vy * vy));
    float c0 = vx * invn, s0 = vy * invn;
    float csv[3], snv[3];
    csv[0] = c0;                        snv[0] = s0;
    csv[1] = c0 * COS_A - s0 * SIN_A;   snv[1] = s0 * COS_A + c0 * SIN_A;
    csv[2] = c0 * COS_A + s0 * SIN_A;   snv[2] = s0 * COS_A - c0 * SIN_A;

    float xa[24];
#pragma unroll
    for (int s = 0; s < 3; s++) {
        int cx = (int)rintf(fmaf(SENSOR_LEN, csv[s], px));
        int cy = (int)rintf(fmaf(SENSOR_LEN, snv[s], py));
        int cell = ((cx & (GRID_SZ - 1)) << 10) | (cy & (GRID_SZ - 1));
        float4 a0 = __ldg(&g_boxA[cell]);
        float4 a1 = __ldg(&g_boxB[cell]);
        xa[s * 8 + 0] = a0.x; xa[s * 8 + 1] = a0.y; xa[s * 8 + 2] = a0.z; xa[s * 8 + 3] = a0.w;
        xa[s * 8 + 4] = a1.x; xa[s * 8 + 5] = a1.y; xa[s * 8 + 6] = a1.z; xa[s * 8 + 7] = a1.w;
    }

    // ---- MLP: 4 hidden units per block iter, f32x2 pairs ----
    ull o2[6];
#pragma unroll
    for (int k = 0; k < 6; k++) o2[k] = pk2(sO0[2 * k], sO0[2 * k + 1]);

#pragma unroll 1
    for (int j = 0; j < HID; j += 4) {
        ulonglong2 bu = *reinterpret_cast<const ulonglong2*>(&sb1[j]);
        ull a01 = bu.x, a23 = bu.y;
#pragma unroll
        for (int k = 0; k < 24; k++) {
            ulonglong2 wu = *reinterpret_cast<const ulonglong2*>(&sW1[k * HID + j]);
            ull x2 = pk2(xa[k], xa[k]);          // ALU-pipe mov, overlaps FMA
            a01 = fma2(x2, wu.x, a01);
            a23 = fma2(x2, wu.y, a23);
        }
        float hv[4];
        upk2(a01, hv[0], hv[1]);
        upk2(a23, hv[2], hv[3]);
#pragma unroll
        for (int jj = 0; jj < 4; jj++) {
            float h;
            asm("tanh.approx.f32 %0, %1;" : "=f"(h) : "f"(hv[jj]));
            ull h2 = pk2(h, h);
            const ulonglong2* wp = reinterpret_cast<const ulonglong2*>(&sW2p[(j + jj) * 12]);
            ulonglong2 u0 = wp[0], u1 = wp[1], u2 = wp[2];
            o2[0] = fma2(h2, u0.x, o2[0]); o2[1] = fma2(h2, u0.y, o2[1]);
            o2[2] = fma2(h2, u1.x, o2[2]); o2[3] = fma2(h2, u1.y, o2[3]);
            o2[4] = fma2(h2, u2.x, o2[4]); o2[5] = fma2(h2, u2.y, o2[5]);
        }
    }
    float o[12];
#pragma unroll
    for (int k = 0; k < 6; k++) upk2(o2[k], o[2 * k], o[2 * k + 1]);

    // ---- pos/vel outputs ----
    float nvx = o[0], nvy = o[1];
    float npx = fmaf(nvx, DT, px);
    float npy = fmaf(nvy, DT, py);
    if (npx >= (float)GRID_SZ) npx -= (float)GRID_SZ; else if (npx < 0.f) npx += (float)GRID_SZ;
    if (npy >= (float)GRID_SZ) npy -= (float)GRID_SZ; else if (npy < 0.f) npy += (float)GRID_SZ;
    out[i]            = npx;
    out[N_AG + i]     = npy;
    out[2 * N_AG + i] = nvx;
    out[3 * N_AG + i] = nvy;

    // ---- fused deposit: winner writes relu(cur + DT*dp)*DECAY, resets claim ----
    float* out_lat = out + 4 * N_AG;
    int cell = ((((int)rintf(px)) & 1023) << 10) | (((int)rintf(py)) & 1023);
    if (g_claim[cell] == i) {
#pragma unroll
        for (int c = 0; c < NCH; c++) {
            float cur = __ldg(&lat[(c << 20) | cell]);
            out_lat[(c << 20) | cell] = fmaxf(fmaf(DT, o[2 + c], cur), 0.f) * DECAY;
        }
        g_claim[cell] = -1;   // restore state for next graph replay
    }
}

extern "C" void kernel_launch(void* const* d_in, const int* in_sizes, int n_in,
                              void* d_out, int out_size) {
    const float* pos = (const float*)d_in[0];   // (2, N)
    const float* vel = (const float*)d_in[1];   // (2, N)
    const float* lat = (const float*)d_in[2];   // (8, 1024, 1024)
    const float* W1  = (const float*)d_in[3];   // (24, 64)
    const float* b1  = (const float*)d_in[4];   // (64,)
    const float* W2  = (const float*)d_in[5];   // (64, 10)
    const float* b2  = (const float*)d_in[6];   // (10,)
    float* out = (float*)d_out;
    float* out_lat = out + 4 * N_AG;

    prep_kernel<<<GRID_SZ, 256>>>(lat, pos, out_lat);
    agent_kernel<<<N_AG / 256, 256>>>(pos, vel, W1, b1, W2, b2, lat, out);
}